// round 1
// baseline (speedup 1.0000x reference)
#include <cuda_runtime.h>
#include <cstdint>

typedef unsigned long long u64;

#define HID 32
#define TSEQ 200
#define PSTEPS 50
#define BATCHN 32768

// ---------- packed f32x2 helpers (sm_103a) ----------
__device__ __forceinline__ u64 pack2(float a, float b) {
    u64 r; asm("mov.b64 %0, {%1, %2};" : "=l"(r) : "f"(a), "f"(b)); return r;
}
__device__ __forceinline__ void unpack2(u64 v, float& a, float& b) {
    asm("mov.b64 {%0, %1}, %2;" : "=f"(a), "=f"(b) : "l"(v));
}
__device__ __forceinline__ void fma2(u64& d, u64 a, u64 b) {
    asm("fma.rn.f32x2 %0, %1, %2, %0;" : "+l"(d) : "l"(a), "l"(b));
}
__device__ __forceinline__ u64 add2(u64 a, u64 b) {
    u64 r; asm("add.rn.f32x2 %0, %1, %2;" : "=l"(r) : "l"(a), "l"(b)); return r;
}
// LDS.128 straight into two 64-bit operand registers (no pack movs)
__device__ __forceinline__ void lds2(u64& a, u64& b, uint32_t addr) {
    asm volatile("ld.shared.v2.u64 {%0, %1}, [%2];" : "=l"(a), "=l"(b) : "r"(addr));
}

// ---------- fast activations ----------
__device__ __forceinline__ float fast_ex2(float x) {
    float r; asm("ex2.approx.f32 %0, %1;" : "=f"(r) : "f"(x)); return r;
}
__device__ __forceinline__ float fast_rcp(float x) {
    float r; asm("rcp.approx.f32 %0, %1;" : "=f"(r) : "f"(x)); return r;
}
__device__ __forceinline__ float sigm(float x) {
    // 1/(1+2^(-x*log2e))
    return fast_rcp(1.0f + fast_ex2(-1.4426950408889634f * x));
}
__device__ __forceinline__ float tanh_(float x) {
    // 2/(1+2^(-2x*log2e)) - 1
    return fmaf(2.0f, fast_rcp(1.0f + fast_ex2(-2.8853900817779268f * x)), -1.0f);
}

// One LSTM cell step for this thread's sample.
// h[] : broadcast-pair packed previous hidden state (registers)
// sH/sC : per-thread staging in SMEM (lane-minor, conflict-free)
template <bool CARRY_C>
__device__ __forceinline__ void cell_step(
    float x0, float x1, float x2, float x3,
    u64 (&h)[HID], float* sH, float* sC, int tid,
    uint32_t aWhh, uint32_t aWih, uint32_t aB)
{
    const u64 xq0 = pack2(x0, x0), xq1 = pack2(x1, x1);
    const u64 xq2 = pack2(x2, x2), xq3 = pack2(x3, x3);

#pragma unroll 4
    for (int j = 0; j < HID; j++) {
        // accumulators: (i,f) and (g,o) pairs, 2-way split for ILP
        u64 aif0, ago0;
        lds2(aif0, ago0, aB + (uint32_t)j * 16u);   // bias preloaded into accums
        u64 aif1 = 0ull, ago1 = 0ull;

        // input contribution (4 dims)
        {
            u64 w0, w1;
            lds2(w0, w1, aWih + (uint32_t)(j * 4 + 0) * 16u);
            fma2(aif0, w0, xq0); fma2(ago0, w1, xq0);
            lds2(w0, w1, aWih + (uint32_t)(j * 4 + 1) * 16u);
            fma2(aif1, w0, xq1); fma2(ago1, w1, xq1);
            lds2(w0, w1, aWih + (uint32_t)(j * 4 + 2) * 16u);
            fma2(aif0, w0, xq2); fma2(ago0, w1, xq2);
            lds2(w0, w1, aWih + (uint32_t)(j * 4 + 3) * 16u);
            fma2(aif1, w0, xq3); fma2(ago1, w1, xq3);
        }

        // recurrent contribution (32 dims)
#pragma unroll
        for (int k = 0; k < HID; k += 2) {
            u64 w0, w1, w2, w3;
            lds2(w0, w1, aWhh + (uint32_t)(j * 32 + k) * 16u);
            fma2(aif0, w0, h[k]);     fma2(ago0, w1, h[k]);
            lds2(w2, w3, aWhh + (uint32_t)(j * 32 + k + 1) * 16u);
            fma2(aif1, w2, h[k + 1]); fma2(ago1, w3, h[k + 1]);
        }

        u64 aif = add2(aif0, aif1);
        u64 ago = add2(ago0, ago1);
        float gi, gf, gg, go;
        unpack2(aif, gi, gf);
        unpack2(ago, gg, go);

        float si = sigm(gi);
        float tg = tanh_(gg);
        float so = sigm(go);
        float cn;
        if (CARRY_C) {
            float cv = sC[j * 32 + tid];
            cn = sigm(gf) * cv + si * tg;
            sC[j * 32 + tid] = cn;
        } else {
            // decode resets cell state to zero each step
            cn = si * tg;
        }
        sH[j * 32 + tid] = so * tanh_(cn);
    }

    // refresh register copy of h (packed broadcast pairs)
#pragma unroll
    for (int k = 0; k < HID; k++) {
        float v = sH[k * 32 + tid];
        h[k] = pack2(v, v);
    }
}

__global__ void __launch_bounds__(32, 8) lstm_kernel(
    const float* __restrict__ hist,
    const float* __restrict__ Wih,
    const float* __restrict__ Whh,
    const float* __restrict__ bih,
    const float* __restrict__ bhh,
    const float* __restrict__ Wpred,
    const float* __restrict__ bpred,
    float* __restrict__ out)
{
    // gate-interleaved weights: quad (Wi,Wf,Wg,Wo) per (j,k)
    __shared__ float sWhh[HID * HID * 4];  // 16 KB
    __shared__ float sWih[HID * 4 * 4];    // 2 KB
    __shared__ float sB[HID * 4];          // 512 B
    __shared__ float sWp[4 * HID];         // 512 B
    __shared__ float sbp[4];
    __shared__ float sH[HID * 32];         // per-lane hidden staging, 4 KB
    __shared__ float sC[HID * 32];         // per-lane cell state, 4 KB

    const int tid = threadIdx.x;

    // ---- pack weights into SMEM ----
    for (int idx = tid; idx < HID * HID; idx += 32) {
        int j = idx >> 5, k = idx & 31;
        sWhh[idx * 4 + 0] = Whh[(0 * HID + j) * HID + k];
        sWhh[idx * 4 + 1] = Whh[(1 * HID + j) * HID + k];
        sWhh[idx * 4 + 2] = Whh[(2 * HID + j) * HID + k];
        sWhh[idx * 4 + 3] = Whh[(3 * HID + j) * HID + k];
    }
    for (int idx = tid; idx < HID * 4; idx += 32) {
        int j = idx >> 2, d = idx & 3;
        sWih[idx * 4 + 0] = Wih[(0 * HID + j) * 4 + d];
        sWih[idx * 4 + 1] = Wih[(1 * HID + j) * 4 + d];
        sWih[idx * 4 + 2] = Wih[(2 * HID + j) * 4 + d];
        sWih[idx * 4 + 3] = Wih[(3 * HID + j) * 4 + d];
    }
    {
        int j = tid;
        sB[j * 4 + 0] = bih[0 * HID + j] + bhh[0 * HID + j];
        sB[j * 4 + 1] = bih[1 * HID + j] + bhh[1 * HID + j];
        sB[j * 4 + 2] = bih[2 * HID + j] + bhh[2 * HID + j];
        sB[j * 4 + 3] = bih[3 * HID + j] + bhh[3 * HID + j];
    }
    for (int idx = tid; idx < 4 * HID; idx += 32) sWp[idx] = Wpred[idx];
    if (tid < 4) sbp[tid] = bpred[tid];
    __syncthreads();

    const uint32_t aWhh = (uint32_t)__cvta_generic_to_shared(sWhh);
    const uint32_t aWih = (uint32_t)__cvta_generic_to_shared(sWih);
    const uint32_t aB   = (uint32_t)__cvta_generic_to_shared(sB);

    const int b = blockIdx.x * 32 + tid;   // one sample per thread
    const float4* xp = (const float4*)(hist + (size_t)b * (TSEQ * 4));

    u64 h[HID];
#pragma unroll
    for (int k = 0; k < HID; k++) h[k] = 0ull;
#pragma unroll
    for (int j = 0; j < HID; j++) sC[j * 32 + tid] = 0.0f;

    // ---- encoder: 200 steps ----
    for (int t = 0; t < TSEQ; t++) {
        float4 x = xp[t];
        cell_step<true>(x.x, x.y, x.z, x.w, h, sH, sC, tid, aWhh, aWih, aB);
    }

    // ---- autoregressive decode: 50 steps (cell state reset each step) ----
    float4* op = (float4*)(out + (size_t)b * (PSTEPS * 4));
    for (int p = 0; p < PSTEPS; p++) {
        // pred = h @ W_pred^T + b_pred (fp32, exact match to reference)
        float hs[HID];
#pragma unroll
        for (int k = 0; k < HID; k++) {
            float a, bb; unpack2(h[k], a, bb); hs[k] = a;
        }
        float pr0 = sbp[0], pr1 = sbp[1], pr2 = sbp[2], pr3 = sbp[3];
#pragma unroll
        for (int k = 0; k < HID; k++) {
            pr0 = fmaf(sWp[0 * HID + k], hs[k], pr0);
            pr1 = fmaf(sWp[1 * HID + k], hs[k], pr1);
            pr2 = fmaf(sWp[2 * HID + k], hs[k], pr2);
            pr3 = fmaf(sWp[3 * HID + k], hs[k], pr3);
        }
        op[p] = make_float4(pr0, pr1, pr2, pr3);

        cell_step<false>(pr0, pr1, pr2, pr3, h, sH, sC, tid, aWhh, aWih, aB);
    }
}

extern "C" void kernel_launch(void* const* d_in, const int* in_sizes, int n_in,
                              void* d_out, int out_size) {
    const float* hist  = (const float*)d_in[0];
    const float* Wih   = (const float*)d_in[1];
    const float* Whh   = (const float*)d_in[2];
    const float* bih   = (const float*)d_in[3];
    const float* bhh   = (const float*)d_in[4];
    const float* Wpred = (const float*)d_in[5];
    const float* bpred = (const float*)d_in[6];
    lstm_kernel<<<BATCHN / 32, 32>>>(hist, Wih, Whh, bih, bhh, Wpred, bpred,
                                     (float*)d_out);
}

// round 2
// speedup vs baseline: 1.0560x; 1.0560x over previous
#include <cuda_runtime.h>
#include <cstdint>

typedef unsigned long long u64;

#define HID 32
#define TSEQ 200
#define PSTEPS 50
#define BATCHN 32768

// ---------- packed f32x2 helpers (sm_103a) ----------
__device__ __forceinline__ u64 pack2(float a, float b) {
    u64 r; asm("mov.b64 %0, {%1, %2};" : "=l"(r) : "f"(a), "f"(b)); return r;
}
__device__ __forceinline__ void unpack2(u64 v, float& a, float& b) {
    asm("mov.b64 {%0, %1}, %2;" : "=f"(a), "=f"(b) : "l"(v));
}
__device__ __forceinline__ void fma2(u64& d, u64 a, u64 b) {
    asm("fma.rn.f32x2 %0, %1, %2, %0;" : "+l"(d) : "l"(a), "l"(b));
}
__device__ __forceinline__ u64 add2(u64 a, u64 b) {
    u64 r; asm("add.rn.f32x2 %0, %1, %2;" : "=l"(r) : "l"(a), "l"(b)); return r;
}
// LDS.128 straight into two 64-bit operand registers (no pack movs)
__device__ __forceinline__ void lds2(u64& a, u64& b, uint32_t addr) {
    asm volatile("ld.shared.v2.u64 {%0, %1}, [%2];" : "=l"(a), "=l"(b) : "r"(addr));
}

// ---------- fast activations ----------
__device__ __forceinline__ float fast_ex2(float x) {
    float r; asm("ex2.approx.f32 %0, %1;" : "=f"(r) : "f"(x)); return r;
}
__device__ __forceinline__ float fast_rcp(float x) {
    float r; asm("rcp.approx.f32 %0, %1;" : "=f"(r) : "f"(x)); return r;
}
__device__ __forceinline__ float sigm(float x) {
    // 1/(1+2^(-x*log2e))
    return fast_rcp(1.0f + fast_ex2(-1.4426950408889634f * x));
}
__device__ __forceinline__ float tanh_(float x) {
    // 2/(1+2^(-2x*log2e)) - 1
    return fmaf(2.0f, fast_rcp(1.0f + fast_ex2(-2.8853900817779268f * x)), -1.0f);
}

// One LSTM cell step for this thread's sample.
// h[] : broadcast-pair packed previous hidden state (registers)
// sH/sC : per-thread staging in SMEM (lane-minor, conflict-free)
template <bool CARRY_C>
__device__ __forceinline__ void cell_step(
    float x0, float x1, float x2, float x3,
    u64 (&h)[HID], float* sH, float* sC, int tid,
    uint32_t aWhh, uint32_t aWih, uint32_t aB)
{
    const u64 xq0 = pack2(x0, x0), xq1 = pack2(x1, x1);
    const u64 xq2 = pack2(x2, x2), xq3 = pack2(x3, x3);

#pragma unroll 4
    for (int j = 0; j < HID; j++) {
        // accumulators: (i,f) and (g,o) pairs, 2-way split for ILP
        u64 aif0, ago0;
        lds2(aif0, ago0, aB + (uint32_t)j * 16u);   // bias preloaded into accums
        u64 aif1 = 0ull, ago1 = 0ull;

        // input contribution (4 dims)
        {
            u64 w0, w1;
            lds2(w0, w1, aWih + (uint32_t)(j * 4 + 0) * 16u);
            fma2(aif0, w0, xq0); fma2(ago0, w1, xq0);
            lds2(w0, w1, aWih + (uint32_t)(j * 4 + 1) * 16u);
            fma2(aif1, w0, xq1); fma2(ago1, w1, xq1);
            lds2(w0, w1, aWih + (uint32_t)(j * 4 + 2) * 16u);
            fma2(aif0, w0, xq2); fma2(ago0, w1, xq2);
            lds2(w0, w1, aWih + (uint32_t)(j * 4 + 3) * 16u);
            fma2(aif1, w0, xq3); fma2(ago1, w1, xq3);
        }

        // recurrent contribution (32 dims)
#pragma unroll
        for (int k = 0; k < HID; k += 2) {
            u64 w0, w1, w2, w3;
            lds2(w0, w1, aWhh + (uint32_t)(j * 32 + k) * 16u);
            fma2(aif0, w0, h[k]);     fma2(ago0, w1, h[k]);
            lds2(w2, w3, aWhh + (uint32_t)(j * 32 + k + 1) * 16u);
            fma2(aif1, w2, h[k + 1]); fma2(ago1, w3, h[k + 1]);
        }

        u64 aif = add2(aif0, aif1);
        u64 ago = add2(ago0, ago1);
        float gi, gf, gg, go;
        unpack2(aif, gi, gf);
        unpack2(ago, gg, go);

        float si = sigm(gi);
        float tg = tanh_(gg);
        float so = sigm(go);
        float cn;
        if (CARRY_C) {
            float cv = sC[j * 32 + tid];
            cn = sigm(gf) * cv + si * tg;
            sC[j * 32 + tid] = cn;
        } else {
            // decode resets cell state to zero each step
            cn = si * tg;
        }
        sH[j * 32 + tid] = so * tanh_(cn);
    }

    // refresh register copy of h (packed broadcast pairs)
#pragma unroll
    for (int k = 0; k < HID; k++) {
        float v = sH[k * 32 + tid];
        h[k] = pack2(v, v);
    }
}

__global__ void __launch_bounds__(32, 8) lstm_kernel(
    const float* __restrict__ hist,
    const float* __restrict__ Wih,
    const float* __restrict__ Whh,
    const float* __restrict__ bih,
    const float* __restrict__ bhh,
    const float* __restrict__ Wpred,
    const float* __restrict__ bpred,
    float* __restrict__ out)
{
    // gate-interleaved weights: quad (Wi,Wf,Wg,Wo) per (j,k)
    __shared__ float sWhh[HID * HID * 4];  // 16 KB
    __shared__ float sWih[HID * 4 * 4];    // 2 KB
    __shared__ float sB[HID * 4];          // 512 B
    __shared__ float sWp[4 * HID];         // 512 B
    __shared__ float sbp[4];
    __shared__ float sH[HID * 32];         // per-lane hidden staging, 4 KB
    __shared__ float sC[HID * 32];         // per-lane cell state, 4 KB

    const int tid = threadIdx.x;

    // ---- pack weights into SMEM ----
    for (int idx = tid; idx < HID * HID; idx += 32) {
        int j = idx >> 5, k = idx & 31;
        sWhh[idx * 4 + 0] = Whh[(0 * HID + j) * HID + k];
        sWhh[idx * 4 + 1] = Whh[(1 * HID + j) * HID + k];
        sWhh[idx * 4 + 2] = Whh[(2 * HID + j) * HID + k];
        sWhh[idx * 4 + 3] = Whh[(3 * HID + j) * HID + k];
    }
    for (int idx = tid; idx < HID * 4; idx += 32) {
        int j = idx >> 2, d = idx & 3;
        sWih[idx * 4 + 0] = Wih[(0 * HID + j) * 4 + d];
        sWih[idx * 4 + 1] = Wih[(1 * HID + j) * 4 + d];
        sWih[idx * 4 + 2] = Wih[(2 * HID + j) * 4 + d];
        sWih[idx * 4 + 3] = Wih[(3 * HID + j) * 4 + d];
    }
    {
        int j = tid;
        sB[j * 4 + 0] = bih[0 * HID + j] + bhh[0 * HID + j];
        sB[j * 4 + 1] = bih[1 * HID + j] + bhh[1 * HID + j];
        sB[j * 4 + 2] = bih[2 * HID + j] + bhh[2 * HID + j];
        sB[j * 4 + 3] = bih[3 * HID + j] + bhh[3 * HID + j];
    }
    for (int idx = tid; idx < 4 * HID; idx += 32) sWp[idx] = Wpred[idx];
    if (tid < 4) sbp[tid] = bpred[tid];
    __syncthreads();

    const uint32_t aWhh = (uint32_t)__cvta_generic_to_shared(sWhh);
    const uint32_t aWih = (uint32_t)__cvta_generic_to_shared(sWih);
    const uint32_t aB   = (uint32_t)__cvta_generic_to_shared(sB);

    const int b = blockIdx.x * 32 + tid;   // one sample per thread
    const float4* xp = (const float4*)(hist + (size_t)b * (TSEQ * 4));

    u64 h[HID];
#pragma unroll
    for (int k = 0; k < HID; k++) h[k] = 0ull;
#pragma unroll
    for (int j = 0; j < HID; j++) sC[j * 32 + tid] = 0.0f;

    // ---- encoder: 200 steps ----
    for (int t = 0; t < TSEQ; t++) {
        float4 x = xp[t];
        cell_step<true>(x.x, x.y, x.z, x.w, h, sH, sC, tid, aWhh, aWih, aB);
    }

    // ---- autoregressive decode: 50 steps (cell state reset each step) ----
    float4* op = (float4*)(out + (size_t)b * (PSTEPS * 4));
    for (int p = 0; p < PSTEPS; p++) {
        // pred = h @ W_pred^T + b_pred (fp32, exact match to reference)
        float hs[HID];
#pragma unroll
        for (int k = 0; k < HID; k++) {
            float a, bb; unpack2(h[k], a, bb); hs[k] = a;
        }
        float pr0 = sbp[0], pr1 = sbp[1], pr2 = sbp[2], pr3 = sbp[3];
#pragma unroll
        for (int k = 0; k < HID; k++) {
            pr0 = fmaf(sWp[0 * HID + k], hs[k], pr0);
            pr1 = fmaf(sWp[1 * HID + k], hs[k], pr1);
            pr2 = fmaf(sWp[2 * HID + k], hs[k], pr2);
            pr3 = fmaf(sWp[3 * HID + k], hs[k], pr3);
        }
        op[p] = make_float4(pr0, pr1, pr2, pr3);

        cell_step<false>(pr0, pr1, pr2, pr3, h, sH, sC, tid, aWhh, aWih, aB);
    }
}

extern "C" void kernel_launch(void* const* d_in, const int* in_sizes, int n_in,
                              void* d_out, int out_size) {
    const float* hist  = (const float*)d_in[0];
    const float* Wih   = (const float*)d_in[1];
    const float* Whh   = (const float*)d_in[2];
    const float* bih   = (const float*)d_in[3];
    const float* bhh   = (const float*)d_in[4];
    const float* Wpred = (const float*)d_in[5];
    const float* bpred = (const float*)d_in[6];
    lstm_kernel<<<BATCHN / 32, 32>>>(hist, Wih, Whh, bih, bhh, Wpred, bpred,
                                     (float*)d_out);
}

// round 3
// speedup vs baseline: 1.0563x; 1.0003x over previous
#include <cuda_runtime.h>
#include <cstdint>

typedef unsigned long long u64;

#define HID 32
#define TSEQ 200
#define PSTEPS 50
#define BATCHN 32768

// ---------- packed f32x2 helpers (sm_103a) ----------
__device__ __forceinline__ u64 pack2(float a, float b) {
    u64 r; asm("mov.b64 %0, {%1, %2};" : "=l"(r) : "f"(a), "f"(b)); return r;
}
__device__ __forceinline__ void unpack2(u64 v, float& a, float& b) {
    asm("mov.b64 {%0, %1}, %2;" : "=f"(a), "=f"(b) : "l"(v));
}
__device__ __forceinline__ void fma2(u64& d, u64 a, u64 b) {
    asm("fma.rn.f32x2 %0, %1, %2, %0;" : "+l"(d) : "l"(a), "l"(b));
}
__device__ __forceinline__ u64 add2(u64 a, u64 b) {
    u64 r; asm("add.rn.f32x2 %0, %1, %2;" : "=l"(r) : "l"(a), "l"(b)); return r;
}
// LDS.128 straight into two 64-bit operand registers (no pack movs)
__device__ __forceinline__ void lds2(u64& a, u64& b, uint32_t addr) {
    asm volatile("ld.shared.v2.u64 {%0, %1}, [%2];" : "=l"(a), "=l"(b) : "r"(addr));
}

// ---------- fast activations ----------
__device__ __forceinline__ float fast_ex2(float x) {
    float r; asm("ex2.approx.f32 %0, %1;" : "=f"(r) : "f"(x)); return r;
}
__device__ __forceinline__ float fast_rcp(float x) {
    float r; asm("rcp.approx.f32 %0, %1;" : "=f"(r) : "f"(x)); return r;
}
__device__ __forceinline__ float sigm(float x) {
    // 1/(1+2^(-x*log2e))
    return fast_rcp(1.0f + fast_ex2(-1.4426950408889634f * x));
}
__device__ __forceinline__ float tanh_(float x) {
    // 2/(1+2^(-2x*log2e)) - 1
    return fmaf(2.0f, fast_rcp(1.0f + fast_ex2(-2.8853900817779268f * x)), -1.0f);
}

// One LSTM cell step for this thread's sample.
// h[] : broadcast-pair packed previous hidden state (registers)
// sH/sC : per-thread staging in SMEM (lane-minor, conflict-free)
template <bool CARRY_C>
__device__ __forceinline__ void cell_step(
    float x0, float x1, float x2, float x3,
    u64 (&h)[HID], float* sH, float* sC, int tid,
    uint32_t aWhh, uint32_t aWih, uint32_t aB)
{
    const u64 xq0 = pack2(x0, x0), xq1 = pack2(x1, x1);
    const u64 xq2 = pack2(x2, x2), xq3 = pack2(x3, x3);

#pragma unroll 4
    for (int j = 0; j < HID; j++) {
        // accumulators: (i,f) and (g,o) pairs, 2-way split for ILP
        u64 aif0, ago0;
        lds2(aif0, ago0, aB + (uint32_t)j * 16u);   // bias preloaded into accums
        u64 aif1 = 0ull, ago1 = 0ull;

        // input contribution (4 dims)
        {
            u64 w0, w1;
            lds2(w0, w1, aWih + (uint32_t)(j * 4 + 0) * 16u);
            fma2(aif0, w0, xq0); fma2(ago0, w1, xq0);
            lds2(w0, w1, aWih + (uint32_t)(j * 4 + 1) * 16u);
            fma2(aif1, w0, xq1); fma2(ago1, w1, xq1);
            lds2(w0, w1, aWih + (uint32_t)(j * 4 + 2) * 16u);
            fma2(aif0, w0, xq2); fma2(ago0, w1, xq2);
            lds2(w0, w1, aWih + (uint32_t)(j * 4 + 3) * 16u);
            fma2(aif1, w0, xq3); fma2(ago1, w1, xq3);
        }

        // recurrent contribution (32 dims)
#pragma unroll
        for (int k = 0; k < HID; k += 2) {
            u64 w0, w1, w2, w3;
            lds2(w0, w1, aWhh + (uint32_t)(j * 32 + k) * 16u);
            fma2(aif0, w0, h[k]);     fma2(ago0, w1, h[k]);
            lds2(w2, w3, aWhh + (uint32_t)(j * 32 + k + 1) * 16u);
            fma2(aif1, w2, h[k + 1]); fma2(ago1, w3, h[k + 1]);
        }

        u64 aif = add2(aif0, aif1);
        u64 ago = add2(ago0, ago1);
        float gi, gf, gg, go;
        unpack2(aif, gi, gf);
        unpack2(ago, gg, go);

        float si = sigm(gi);
        float tg = tanh_(gg);
        float so = sigm(go);
        float cn;
        if (CARRY_C) {
            float cv = sC[j * 32 + tid];
            cn = sigm(gf) * cv + si * tg;
            sC[j * 32 + tid] = cn;
        } else {
            // decode resets cell state to zero each step
            cn = si * tg;
        }
        sH[j * 32 + tid] = so * tanh_(cn);
    }

    // refresh register copy of h (packed broadcast pairs)
#pragma unroll
    for (int k = 0; k < HID; k++) {
        float v = sH[k * 32 + tid];
        h[k] = pack2(v, v);
    }
}

__global__ void __launch_bounds__(32, 8) lstm_kernel(
    const float* __restrict__ hist,
    const float* __restrict__ Wih,
    const float* __restrict__ Whh,
    const float* __restrict__ bih,
    const float* __restrict__ bhh,
    const float* __restrict__ Wpred,
    const float* __restrict__ bpred,
    float* __restrict__ out)
{
    // gate-interleaved weights: quad (Wi,Wf,Wg,Wo) per (j,k)
    __shared__ float sWhh[HID * HID * 4];  // 16 KB
    __shared__ float sWih[HID * 4 * 4];    // 2 KB
    __shared__ float sB[HID * 4];          // 512 B
    __shared__ float sWp[4 * HID];         // 512 B
    __shared__ float sbp[4];
    __shared__ float sH[HID * 32];         // per-lane hidden staging, 4 KB
    __shared__ float sC[HID * 32];         // per-lane cell state, 4 KB

    const int tid = threadIdx.x;

    // ---- pack weights into SMEM ----
    for (int idx = tid; idx < HID * HID; idx += 32) {
        int j = idx >> 5, k = idx & 31;
        sWhh[idx * 4 + 0] = Whh[(0 * HID + j) * HID + k];
        sWhh[idx * 4 + 1] = Whh[(1 * HID + j) * HID + k];
        sWhh[idx * 4 + 2] = Whh[(2 * HID + j) * HID + k];
        sWhh[idx * 4 + 3] = Whh[(3 * HID + j) * HID + k];
    }
    for (int idx = tid; idx < HID * 4; idx += 32) {
        int j = idx >> 2, d = idx & 3;
        sWih[idx * 4 + 0] = Wih[(0 * HID + j) * 4 + d];
        sWih[idx * 4 + 1] = Wih[(1 * HID + j) * 4 + d];
        sWih[idx * 4 + 2] = Wih[(2 * HID + j) * 4 + d];
        sWih[idx * 4 + 3] = Wih[(3 * HID + j) * 4 + d];
    }
    {
        int j = tid;
        sB[j * 4 + 0] = bih[0 * HID + j] + bhh[0 * HID + j];
        sB[j * 4 + 1] = bih[1 * HID + j] + bhh[1 * HID + j];
        sB[j * 4 + 2] = bih[2 * HID + j] + bhh[2 * HID + j];
        sB[j * 4 + 3] = bih[3 * HID + j] + bhh[3 * HID + j];
    }
    for (int idx = tid; idx < 4 * HID; idx += 32) sWp[idx] = Wpred[idx];
    if (tid < 4) sbp[tid] = bpred[tid];
    __syncthreads();

    const uint32_t aWhh = (uint32_t)__cvta_generic_to_shared(sWhh);
    const uint32_t aWih = (uint32_t)__cvta_generic_to_shared(sWih);
    const uint32_t aB   = (uint32_t)__cvta_generic_to_shared(sB);

    const int b = blockIdx.x * 32 + tid;   // one sample per thread
    const float4* xp = (const float4*)(hist + (size_t)b * (TSEQ * 4));

    u64 h[HID];
#pragma unroll
    for (int k = 0; k < HID; k++) h[k] = 0ull;
#pragma unroll
    for (int j = 0; j < HID; j++) sC[j * 32 + tid] = 0.0f;

    // ---- encoder: 200 steps ----
    for (int t = 0; t < TSEQ; t++) {
        float4 x = xp[t];
        cell_step<true>(x.x, x.y, x.z, x.w, h, sH, sC, tid, aWhh, aWih, aB);
    }

    // ---- autoregressive decode: 50 steps (cell state reset each step) ----
    float4* op = (float4*)(out + (size_t)b * (PSTEPS * 4));
    for (int p = 0; p < PSTEPS; p++) {
        // pred = h @ W_pred^T + b_pred (fp32, exact match to reference)
        float hs[HID];
#pragma unroll
        for (int k = 0; k < HID; k++) {
            float a, bb; unpack2(h[k], a, bb); hs[k] = a;
        }
        float pr0 = sbp[0], pr1 = sbp[1], pr2 = sbp[2], pr3 = sbp[3];
#pragma unroll
        for (int k = 0; k < HID; k++) {
            pr0 = fmaf(sWp[0 * HID + k], hs[k], pr0);
            pr1 = fmaf(sWp[1 * HID + k], hs[k], pr1);
            pr2 = fmaf(sWp[2 * HID + k], hs[k], pr2);
            pr3 = fmaf(sWp[3 * HID + k], hs[k], pr3);
        }
        op[p] = make_float4(pr0, pr1, pr2, pr3);

        cell_step<false>(pr0, pr1, pr2, pr3, h, sH, sC, tid, aWhh, aWih, aB);
    }
}

extern "C" void kernel_launch(void* const* d_in, const int* in_sizes, int n_in,
                              void* d_out, int out_size) {
    const float* hist  = (const float*)d_in[0];
    const float* Wih   = (const float*)d_in[1];
    const float* Whh   = (const float*)d_in[2];
    const float* bih   = (const float*)d_in[3];
    const float* bhh   = (const float*)d_in[4];
    const float* Wpred = (const float*)d_in[5];
    const float* bpred = (const float*)d_in[6];
    lstm_kernel<<<BATCHN / 32, 32>>>(hist, Wih, Whh, bih, bhh, Wpred, bpred,
                                     (float*)d_out);
}

// round 4
// speedup vs baseline: 1.0767x; 1.0192x over previous
#include <cuda_runtime.h>
#include <cstdint>

typedef unsigned long long u64;

#define HID 32
#define TSEQ 200
#define PSTEPS 50
#define BATCHN 32768

// ---------- packed f32x2 helpers (sm_103a) ----------
__device__ __forceinline__ u64 pack2(float a, float b) {
    u64 r; asm("mov.b64 %0, {%1, %2};" : "=l"(r) : "f"(a), "f"(b)); return r;
}
__device__ __forceinline__ void unpack2(u64 v, float& a, float& b) {
    asm("mov.b64 {%0, %1}, %2;" : "=f"(a), "=f"(b) : "l"(v));
}
__device__ __forceinline__ void fma2(u64& d, u64 a, u64 b) {
    asm("fma.rn.f32x2 %0, %1, %2, %0;" : "+l"(d) : "l"(a), "l"(b));
}
__device__ __forceinline__ u64 add2(u64 a, u64 b) {
    u64 r; asm("add.rn.f32x2 %0, %1, %2;" : "=l"(r) : "l"(a), "l"(b)); return r;
}
// LDS.128 straight into two 64-bit operand registers
__device__ __forceinline__ void lds2(u64& a, u64& b, uint32_t addr) {
    asm volatile("ld.shared.v2.u64 {%0, %1}, [%2];" : "=l"(a), "=l"(b) : "r"(addr));
}

// ---------- fast activations ----------
__device__ __forceinline__ float fast_ex2(float x) {
    float r; asm("ex2.approx.f32 %0, %1;" : "=f"(r) : "f"(x)); return r;
}
__device__ __forceinline__ float fast_rcp(float x) {
    float r; asm("rcp.approx.f32 %0, %1;" : "=f"(r) : "f"(x)); return r;
}
__device__ __forceinline__ float sigm(float x) {
    return fast_rcp(1.0f + fast_ex2(-1.4426950408889634f * x));
}
__device__ __forceinline__ float tanh_(float x) {
    return fmaf(2.0f, fast_rcp(1.0f + fast_ex2(-2.8853900817779268f * x)), -1.0f);
}

// One LSTM cell step; this thread computes its 16 hidden units (local q),
// then exchanges new-h with its pair lane via shfl.
// h[] : 32 packed broadcast pairs, thread-local order (abs = local ^ (half*16))
// c[] : this thread's 16 cell states (registers). Decode zeroes c before call.
__device__ __forceinline__ void cell16(
    float x0, float x1, float x2, float x3,
    u64 (&h)[HID], float (&c)[16],
    uint32_t bB, uint32_t bWih, uint32_t bWrow0,
    uint32_t colA, uint32_t colB)
{
    const u64 xq0 = pack2(x0, x0), xq1 = pack2(x1, x1);
    const u64 xq2 = pack2(x2, x2), xq3 = pack2(x3, x3);

    float hnew[16];

#pragma unroll
    for (int q = 0; q < 16; q++) {
        const uint32_t row = bWrow0 + (uint32_t)q * 512u;
        u64 aif0, ago0;
        lds2(aif0, ago0, bB + (uint32_t)q * 16u);   // bias preloaded into accums
        u64 aif1 = 0ull, ago1 = 0ull;

        // input contribution (4 dims)
        {
            u64 w0, w1;
            lds2(w0, w1, bWih + (uint32_t)q * 64u + 0u);
            fma2(aif0, w0, xq0); fma2(ago0, w1, xq0);
            lds2(w0, w1, bWih + (uint32_t)q * 64u + 16u);
            fma2(aif1, w0, xq1); fma2(ago1, w1, xq1);
            lds2(w0, w1, bWih + (uint32_t)q * 64u + 32u);
            fma2(aif0, w0, xq2); fma2(ago0, w1, xq2);
            lds2(w0, w1, bWih + (uint32_t)q * 64u + 48u);
            fma2(aif1, w0, xq3); fma2(ago1, w1, xq3);
        }

        // recurrent: own half (local k 0..15)
#pragma unroll
        for (int k = 0; k < 16; k += 2) {
            u64 u0, u1, u2, u3;
            lds2(u0, u1, row + colA + (uint32_t)k * 16u);
            fma2(aif0, u0, h[k]);     fma2(ago0, u1, h[k]);
            lds2(u2, u3, row + colA + (uint32_t)k * 16u + 16u);
            fma2(aif1, u2, h[k + 1]); fma2(ago1, u3, h[k + 1]);
        }
        // recurrent: partner half (local k 16..31)
#pragma unroll
        for (int k = 0; k < 16; k += 2) {
            u64 u0, u1, u2, u3;
            lds2(u0, u1, row + colB + (uint32_t)k * 16u);
            fma2(aif0, u0, h[16 + k]);     fma2(ago0, u1, h[16 + k]);
            lds2(u2, u3, row + colB + (uint32_t)k * 16u + 16u);
            fma2(aif1, u2, h[17 + k]); fma2(ago1, u3, h[17 + k]);
        }

        u64 aif = add2(aif0, aif1);
        u64 ago = add2(ago0, ago1);
        float gi, gf, gg, go;
        unpack2(aif, gi, gf);
        unpack2(ago, gg, go);

        float si = sigm(gi);
        float tg = tanh_(gg);
        float so = sigm(go);
        float cn = fmaf(sigm(gf), c[q], si * tg);
        c[q] = cn;
        hnew[q] = so * tanh_(cn);
    }

    // commit own half + exchange partner half via shfl (pair = adjacent lanes)
#pragma unroll
    for (int q = 0; q < 16; q++) {
        float v = hnew[q];
        h[q] = pack2(v, v);
        float pv = __shfl_xor_sync(0xffffffffu, v, 1);
        h[16 + q] = pack2(pv, pv);
    }
}

__global__ void __launch_bounds__(64, 7) lstm_kernel(
    const float* __restrict__ hist,
    const float* __restrict__ Wih,
    const float* __restrict__ Whh,
    const float* __restrict__ bih,
    const float* __restrict__ bhh,
    const float* __restrict__ Wpred,
    const float* __restrict__ bpred,
    float* __restrict__ out)
{
    // gate-interleaved quads (Wi,Wf,Wg,Wo). The j>=16 (k>=16 for sWp) half is
    // skewed by 16 bytes so the two half-lanes of a warp hit disjoint banks.
    __shared__ __align__(16) float sWhh[HID * HID * 4 + 4];  // ~16.4 KB
    __shared__ __align__(16) float sWih[HID * 4 * 4 + 4];
    __shared__ __align__(16) float sB[HID * 4 + 4];
    __shared__ __align__(16) float sWp[HID * 4 + 4];

    const int tid = threadIdx.x;

    // ---- pack weights into SMEM (skewed) ----
    for (int idx = tid; idx < HID * HID; idx += 64) {
        int j = idx >> 5, k = idx & 31;
        int off = idx * 4 + ((j >= 16) ? 4 : 0);
        sWhh[off + 0] = Whh[(0 * HID + j) * HID + k];
        sWhh[off + 1] = Whh[(1 * HID + j) * HID + k];
        sWhh[off + 2] = Whh[(2 * HID + j) * HID + k];
        sWhh[off + 3] = Whh[(3 * HID + j) * HID + k];
    }
    for (int idx = tid; idx < HID * 4; idx += 64) {
        int j = idx >> 2, d = idx & 3;
        int off = idx * 4 + ((j >= 16) ? 4 : 0);
        sWih[off + 0] = Wih[(0 * HID + j) * 4 + d];
        sWih[off + 1] = Wih[(1 * HID + j) * 4 + d];
        sWih[off + 2] = Wih[(2 * HID + j) * 4 + d];
        sWih[off + 3] = Wih[(3 * HID + j) * 4 + d];
    }
    if (tid < HID) {
        int j = tid;
        int off = j * 4 + ((j >= 16) ? 4 : 0);
        sB[off + 0] = bih[0 * HID + j] + bhh[0 * HID + j];
        sB[off + 1] = bih[1 * HID + j] + bhh[1 * HID + j];
        sB[off + 2] = bih[2 * HID + j] + bhh[2 * HID + j];
        sB[off + 3] = bih[3 * HID + j] + bhh[3 * HID + j];
        // W_pred is [4, 32]; quad per k = (Wp0,Wp1,Wp2,Wp3)[k]
        sWp[off + 0] = Wpred[0 * HID + j];
        sWp[off + 1] = Wpred[1 * HID + j];
        sWp[off + 2] = Wpred[2 * HID + j];
        sWp[off + 3] = Wpred[3 * HID + j];
    }
    __syncthreads();

    const uint32_t aWhh = (uint32_t)__cvta_generic_to_shared(sWhh);
    const uint32_t aWih = (uint32_t)__cvta_generic_to_shared(sWih);
    const uint32_t aB   = (uint32_t)__cvta_generic_to_shared(sB);
    const uint32_t aWp  = (uint32_t)__cvta_generic_to_shared(sWp);

    const uint32_t half = (uint32_t)(tid & 1);          // which 16 hidden units
    const int b = blockIdx.x * 32 + (tid >> 1);          // sample (pair of lanes)

    // per-thread skewed base addresses
    const uint32_t bB     = aB   + half * 272u;          // own bias quads
    const uint32_t bWih   = aWih + half * 1040u;         // own input-weight quads
    const uint32_t bWrow0 = aWhh + half * 8208u;         // own Whh rows
    const uint32_t colA   = half * 256u;                 // own-half columns
    const uint32_t colB   = 256u - half * 256u;          // partner-half columns
    const uint32_t bPA    = aWp + half * 272u;           // pred: own-half ks
    const uint32_t bPB    = aWp + (1u - half) * 272u;    // pred: partner-half ks

    const u64 bp01 = pack2(bpred[0], bpred[1]);
    const u64 bp23 = pack2(bpred[2], bpred[3]);

    u64 h[HID];
    float c[16];
#pragma unroll
    for (int k = 0; k < HID; k++) h[k] = 0ull;
#pragma unroll
    for (int q = 0; q < 16; q++) c[q] = 0.0f;

    // ---- encoder: 200 steps ----
    const float4* xp = (const float4*)(hist + (size_t)b * (TSEQ * 4));
    for (int t = 0; t < TSEQ; t++) {
        float4 x = xp[t];
        cell16(x.x, x.y, x.z, x.w, h, c, bB, bWih, bWrow0, colA, colB);
    }

    // ---- autoregressive decode: 50 steps (cell state reset each step) ----
    float4* op = (float4*)(out + (size_t)b * (PSTEPS * 4));
    for (int p = 0; p < PSTEPS; p++) {
        // pred = h @ W_pred^T + b_pred (full h from both halves)
        u64 pr01 = bp01, pr23 = bp23;
#pragma unroll
        for (int l = 0; l < 16; l++) {
            u64 w0, w1;
            lds2(w0, w1, bPA + (uint32_t)l * 16u);
            fma2(pr01, w0, h[l]); fma2(pr23, w1, h[l]);
        }
#pragma unroll
        for (int l = 0; l < 16; l++) {
            u64 w0, w1;
            lds2(w0, w1, bPB + (uint32_t)l * 16u);
            fma2(pr01, w0, h[16 + l]); fma2(pr23, w1, h[16 + l]);
        }
        float p0, p1, p2, p3;
        unpack2(pr01, p0, p1);
        unpack2(pr23, p2, p3);
        if (!half) op[p] = make_float4(p0, p1, p2, p3);

        // decode resets cell state each step
#pragma unroll
        for (int q = 0; q < 16; q++) c[q] = 0.0f;
        cell16(p0, p1, p2, p3, h, c, bB, bWih, bWrow0, colA, colB);
    }
}

extern "C" void kernel_launch(void* const* d_in, const int* in_sizes, int n_in,
                              void* d_out, int out_size) {
    const float* hist  = (const float*)d_in[0];
    const float* Wih   = (const float*)d_in[1];
    const float* Whh   = (const float*)d_in[2];
    const float* bih   = (const float*)d_in[3];
    const float* bhh   = (const float*)d_in[4];
    const float* Wpred = (const float*)d_in[5];
    const float* bpred = (const float*)d_in[6];
    lstm_kernel<<<BATCHN / 32, 64>>>(hist, Wih, Whh, bih, bhh, Wpred, bpred,
                                     (float*)d_out);
}